// round 16
// baseline (speedup 1.0000x reference)
#include <cuda_runtime.h>
#include <cuda_fp16.h>
#include <math.h>

using u32 = unsigned int;

// ===========================================================================
// Problem constants
// ===========================================================================
static const int BATCH  = 16;
static const int CCH    = 256;
static const int NSP    = 4096;
static const int NSPLIT = 8;     // split-K for logits GEMM

// ===========================================================================
// Device scratch (allocation-free)
// ===========================================================================
__device__ __half g_wih[256 * 512], g_wil[256 * 512];
__device__ __half g_wth[256 * 320], g_wtl[256 * 320];
__device__ __half g_woh[512 * 256], g_wol[512 * 256];
__device__ __half g_imgh[(size_t)BATCH * CCH * NSP];
__device__ __half g_imgl[(size_t)BATCH * CCH * NSP];
__device__ __half g_kvh [(size_t)BATCH * CCH * NSP];
__device__ __half g_kvl [(size_t)BATCH * CCH * NSP];
__device__ __half g_kvTh[(size_t)BATCH * NSP * CCH];
__device__ __half g_tTh [(size_t)BATCH * NSP * CCH];
__device__ float  g_part[(size_t)NSPLIT * BATCH * CCH * CCH];
__device__ __half g_atth[(size_t)BATCH * CCH * CCH];

// ===========================================================================
// PTX helpers (base-target ISA: cp.async / ldmatrix / mma.sync)
// ===========================================================================
__device__ __forceinline__ u32 smem_u32(const void* p) {
    u32 a;
    asm("{ .reg .u64 t; cvta.to.shared.u64 t, %1; cvt.u32.u64 %0, t; }"
        : "=r"(a) : "l"(p));
    return a;
}
__device__ __forceinline__ void cp16(u32 dst, const void* src) {
    asm volatile("cp.async.cg.shared.global [%0], [%1], 16;"
                 :: "r"(dst), "l"(src) : "memory");
}
__device__ __forceinline__ void cp_commit() {
    asm volatile("cp.async.commit_group;" ::: "memory");
}
template <int N>
__device__ __forceinline__ void cp_wait() {
    asm volatile("cp.async.wait_group %0;" :: "n"(N) : "memory");
}
#define LDMX4(d0, d1, d2, d3, addr) \
    asm volatile("ldmatrix.sync.aligned.m8n8.x4.shared.b16 {%0,%1,%2,%3},[%4];" \
                 : "=r"(d0), "=r"(d1), "=r"(d2), "=r"(d3) : "r"(addr))
#define MMA16816(c, a, b0, b1) \
    asm volatile("mma.sync.aligned.m16n8k16.row.col.f32.f16.f16.f32 " \
                 "{%0,%1,%2,%3},{%4,%5,%6,%7},{%8,%9},{%0,%1,%2,%3};" \
                 : "+f"((c)[0]), "+f"((c)[1]), "+f"((c)[2]), "+f"((c)[3]) \
                 : "r"((a)[0]), "r"((a)[1]), "r"((a)[2]), "r"((a)[3]), \
                   "r"(b0), "r"(b1))

__device__ __forceinline__ u32 pack2(__half a, __half b) {
    __half2 h = __halves2half2(a, b);
    return *(u32*)&h;
}

// ===========================================================================
// MERGED FUSED GEMM (stages 1+2 in one launch):
//   z <  16: imgh/imgl = split( w_img @ x1[z] ),      K=512
//   z >= 16: kvh/kvl   = split( w_txt @ x2[z-16] ),   K=320, + kvTh [n,m]
// X fp32 [K,N] transposed + hi/lo split on the fly (double staging buffers).
// 3-pass Markidis. Operand tiles pitch 80B (conflict-free, no XOR).
// __syncthreads-structured pipeline (proven-correct publication semantics).
// ===========================================================================
static const int FT   = 10240;              // one 128x(64B@80B-pitch) tile
static const int FSTG = 8 * FT;             // 81920: staging area offset
static const int SMEM_F = FSTG + 2 * 16384; // 114688

__global__ __launch_bounds__(256, 2)
void gemm_fused(const __half* __restrict__ wih, const __half* __restrict__ wil,
                const float* __restrict__ x1,
                __half* __restrict__ imgh, __half* __restrict__ imgl,
                const __half* __restrict__ wth, const __half* __restrict__ wtl,
                const float* __restrict__ x2,
                __half* __restrict__ kvh, __half* __restrict__ kvl,
                __half* __restrict__ kvTh)
{
    extern __shared__ __align__(128) char sm[];
    const u32 smb = smem_u32(sm);
    const int tid = threadIdx.x;
    const int wid = tid >> 5;
    const int lid = tid & 31;
    const int wm  = wid >> 2;
    const int wn  = wid & 3;

    const int z   = blockIdx.z;
    const bool s2 = (z >= 16);
    const int b   = s2 ? (z - 16) : z;
    const int K   = s2 ? 320 : 512;
    const int m0  = blockIdx.y * 128;
    const int n0  = blockIdx.x * 128;
    const int ldC = 4096;
    const int ldT = 256;

    const __half* Ahm = (s2 ? wth : wih) + (size_t)m0 * K;
    const __half* Alm = (s2 ? wtl : wil) + (size_t)m0 * K;
    const float*  Xb  = (s2 ? x2 : x1) + (size_t)b * K * 4096;

    __half* CHhb = (s2 ? kvh : imgh) + (size_t)b * (256L * 4096);
    __half* CHlb = (s2 ? kvl : imgl) + (size_t)b * (256L * 4096);
    __half* CThb = s2 ? (kvTh + (size_t)b * (4096L * 256)) : nullptr;

    const int rAl = lid & 15;
    const int ksA = lid >> 4;
    const int rBl = ((lid >> 4) & 1) * 8 + (lid & 7);
    const int csB = (lid >> 3) & 1;

    auto cpA = [&](int chunk, int st) {
        const int kt = chunk * 32;
        #pragma unroll
        for (int t = 0; t < 2; t++) {
            const int task = tid + t * 256;
            const int r = task >> 2, c = task & 3;
            const u32 dst = smb + st * (4 * FT) + r * 80 + c * 16;
            cp16(dst,      Ahm + (size_t)r * K + kt + c * 8);
            cp16(dst + FT, Alm + (size_t)r * K + kt + c * 8);
        }
    };
    auto cpB = [&](int chunk) {
        const int kt = chunk * 32;
        const u32 dst0 = smb + FSTG + (chunk & 1) * 16384;
        #pragma unroll
        for (int t = 0; t < 4; t++) {
            const int task = tid + t * 256;
            const int kr = task >> 5, c16 = task & 31;
            cp16(dst0 + kr * 512 + c16 * 16,
                 Xb + (size_t)(kt + kr) * ldC + n0 + c16 * 4);
        }
    };
    auto convB = [&](int chunk) {
        const int st = chunk & 1;
        const float* stg = (const float*)(sm + FSTG + st * 16384);
        #pragma unroll
        for (int t = 0; t < 2; t++) {
            const int task = tid + t * 256;
            const int n = task & 127, ko = task >> 7;
            float f[8];
            #pragma unroll
            for (int i = 0; i < 8; i++)
                f[i] = stg[(ko * 8 + i) * 128 + n];
            __half h[8], l[8];
            #pragma unroll
            for (int i = 0; i < 8; i++) {
                h[i] = __float2half_rn(f[i]);
                l[i] = __float2half_rn(f[i] - __half2float(h[i]));
            }
            uint4 vh = make_uint4(pack2(h[0], h[1]), pack2(h[2], h[3]),
                                  pack2(h[4], h[5]), pack2(h[6], h[7]));
            uint4 vl = make_uint4(pack2(l[0], l[1]), pack2(l[2], l[3]),
                                  pack2(l[4], l[5]), pack2(l[6], l[7]));
            *(uint4*)(sm + st * (4 * FT) + 2 * FT + n * 80 + ko * 16) = vh;
            *(uint4*)(sm + st * (4 * FT) + 3 * FT + n * 80 + ko * 16) = vl;
        }
    };

    const int nC = K >> 5;

    float acc[4][4][4];
    #pragma unroll
    for (int i = 0; i < 4; i++)
        #pragma unroll
        for (int j = 0; j < 4; j++)
            #pragma unroll
            for (int q = 0; q < 4; q++) acc[i][j][q] = 0.0f;

    // prologue: chunks 0,1 (A+B joint groups)
    cpA(0, 0); cpB(0); cp_commit();
    cpA(1, 1); cpB(1); cp_commit();
    cp_wait<1>(); __syncthreads();
    convB(0);
    __syncthreads();

    for (int c = 0; c < nC; c++) {
        const int st = c & 1;
        const u32 tb = smb + st * (4 * FT);
        if (c + 2 < nC) { cpB(c + 2); cp_commit(); }   // early: staging c&1 free
        #pragma unroll
        for (int s16 = 0; s16 < 2; s16++) {
            u32 bh[8], bl[8];
            const u32 rb = (u32)((wn * 32 + rBl) * 80 + (2 * s16 + csB) * 16);
            LDMX4(bh[0], bh[1], bh[2], bh[3], tb + 2 * FT + rb);
            LDMX4(bh[4], bh[5], bh[6], bh[7], tb + 2 * FT + rb + 1280);
            LDMX4(bl[0], bl[1], bl[2], bl[3], tb + 3 * FT + rb);
            LDMX4(bl[4], bl[5], bl[6], bl[7], tb + 3 * FT + rb + 1280);
            #pragma unroll
            for (int mt = 0; mt < 4; mt++) {
                u32 ah[4], al[4];
                const u32 ra = (u32)((wm * 64 + mt * 16 + rAl) * 80 +
                                     (2 * s16 + ksA) * 16);
                LDMX4(ah[0], ah[1], ah[2], ah[3], tb + ra);
                LDMX4(al[0], al[1], al[2], al[3], tb + FT + ra);
                #pragma unroll
                for (int nt = 0; nt < 4; nt++) {
                    MMA16816(acc[mt][nt], ah, bh[2*nt], bh[2*nt+1]);
                    MMA16816(acc[mt][nt], ah, bl[2*nt], bl[2*nt+1]);
                    MMA16816(acc[mt][nt], al, bh[2*nt], bh[2*nt+1]);
                }
            }
        }
        if (c + 1 < nC) {
            if (c + 2 < nC) cp_wait<1>(); else cp_wait<0>();
            __syncthreads();
            convB(c + 1);
            __syncthreads();
            if (c + 2 < nC) { cpA(c + 2, st); cp_commit(); }
        }
    }

    // epilogue
    __syncthreads();
    __half* T = (__half*)sm;   // [128 n][136 m] transpose buffer
    #pragma unroll
    for (int mt = 0; mt < 4; mt++) {
        #pragma unroll
        for (int nt = 0; nt < 4; nt++) {
            const int nn = wn * 32 + nt * 8 + (lid & 3) * 2;
            #pragma unroll
            for (int h = 0; h < 2; h++) {
                const int ml = wm * 64 + mt * 16 + (lid >> 2) + h * 8;
                const int mm = m0 + ml;
                const float v0 = acc[mt][nt][2 * h];
                const float v1 = acc[mt][nt][2 * h + 1];
                const __half h0 = __float2half_rn(v0);
                const __half h1 = __float2half_rn(v1);
                const __half e0 = __float2half_rn(v0 - __half2float(h0));
                const __half e1 = __float2half_rn(v1 - __half2float(h1));
                *(__half2*)(CHhb + (size_t)mm * ldC + n0 + nn) =
                    __halves2half2(h0, h1);
                *(__half2*)(CHlb + (size_t)mm * ldC + n0 + nn) =
                    __halves2half2(e0, e1);
                if (s2) {
                    T[(size_t)nn * 136 + ml]       = h0;
                    T[(size_t)(nn + 1) * 136 + ml] = h1;
                }
            }
        }
    }
    if (s2) {
        __syncthreads();
        #pragma unroll
        for (int it = 0; it < 8; it++) {
            const int idx = it * 256 + tid;
            const int n  = idx >> 4;
            const int ck = idx & 15;
            const uint4 v = *(const uint4*)(T + (size_t)n * 136 + ck * 8);
            *(uint4*)(CThb + (size_t)(n0 + n) * ldT + m0 + ck * 8) = v;
        }
    }
}

// ===========================================================================
// PURE fp16 GEMM (stages 3,5,6), NPASS ∈ {1,2,3}:
//   NPASS=3: AhBh + AhBl + AlBh   (stage 32KB, 3-stage ring)
//   NPASS=1: AhBh                 (stage 16KB, 6-stage ring)
// ===========================================================================
static const int SMEM_TOT = 98304;

template <bool RESID, bool WN, bool WHT, int NPASS>
__global__ __launch_bounds__(256, 2)
void gemm_mma(const __half* __restrict__ Ahg, const __half* __restrict__ Alg,
              const __half* __restrict__ Bhg, const __half* __restrict__ Blg,
              float* __restrict__ Cn, __half* __restrict__ CTh,
              const __half* __restrict__ Rhg, const __half* __restrict__ Rlg,
              const float* __restrict__ gamma,
              int K, int ldA, int ldB, int ldC, int ldT,
              long aBat, long bBat, long cBat, long tBat, int nsplit)
{
    constexpr int NTILE  = 2 + (NPASS >= 2 ? 1 : 0) + (NPASS >= 3 ? 1 : 0);
    constexpr int STRIDE = NTILE * 8192;
    constexpr int NST    = (NPASS == 1) ? 6 : (NPASS == 2 ? 4 : 3);
    constexpr int OB     = (NPASS >= 2) ? 16384 : 8192;

    extern __shared__ __align__(128) char sm[];
    const u32 smb = smem_u32(sm);
    const int tid = threadIdx.x;
    const int wid = tid >> 5;
    const int lid = tid & 31;
    const int wm  = wid >> 2;
    const int wn  = wid & 3;

    const int z = blockIdx.z;
    const int b = z / nsplit;
    const int s = z - b * nsplit;
    const int nbat = gridDim.z / nsplit;

    const __half* Ah = Ahg + (size_t)b * aBat + (size_t)s * K;
    const __half* Al = (NPASS >= 2) ? (Alg + (size_t)b * aBat + (size_t)s * K)
                                    : nullptr;
    const __half* Bh = Bhg + (size_t)b * bBat + (size_t)s * K;
    const __half* Bl = (NPASS >= 3) ? (Blg + (size_t)b * bBat + (size_t)s * K)
                                    : nullptr;

    const size_t ob = (size_t)s * nbat + b;
    float*  Cb   = WN  ? (Cn  + ob * cBat) : nullptr;
    __half* CThb = WHT ? (CTh + ob * tBat) : nullptr;
    const __half* Rh = RESID ? (Rhg + (size_t)b * cBat) : nullptr;
    const __half* Rl = RESID ? (Rlg + (size_t)b * cBat) : nullptr;

    const int m0 = blockIdx.y * 128;
    const int n0 = blockIdx.x * 128;

    const __half* Ahm = Ah + (size_t)m0 * ldA;
    const __half* Alm = (NPASS >= 2) ? (Al + (size_t)m0 * ldA) : nullptr;
    const __half* Bhn = Bh + (size_t)n0 * ldB;
    const __half* Bln = (NPASS >= 3) ? (Bl + (size_t)n0 * ldB) : nullptr;

    const int rAl = lid & 15;
    const int ksA = lid >> 4;
    const int xA  = (rAl >> 1) & 3;
    const int rBl = ((lid >> 4) & 1) * 8 + (lid & 7);
    const int csB = (lid >> 3) & 1;
    const int xB  = (rBl >> 1) & 3;

    auto ldStage = [&](int chunk, int stg) {
        const u32 sb = smb + stg * STRIDE;
        const int kt = chunk * 32;
        #pragma unroll
        for (int p = 0; p < 2; p++) {
            const int idx = tid + p * 256;
            const int r = idx >> 2;
            const int c = idx & 3;
            const u32 soff = r * 64 + ((c ^ ((r >> 1) & 3)) << 4);
            const size_t ga = (size_t)r * ldA + kt + c * 8;
            const size_t gb = (size_t)r * ldB + kt + c * 8;
            cp16(sb + soff, Ahm + ga);
            if constexpr (NPASS >= 2) cp16(sb + 8192 + soff, Alm + ga);
            cp16(sb + OB + soff, Bhn + gb);
            if constexpr (NPASS >= 3) cp16(sb + 24576 + soff, Bln + gb);
        }
    };

    const int nC = K >> 5;

    float acc[4][4][4];
    #pragma unroll
    for (int i = 0; i < 4; i++)
        #pragma unroll
        for (int j = 0; j < 4; j++)
            #pragma unroll
            for (int q = 0; q < 4; q++) acc[i][j][q] = 0.0f;

    #pragma unroll
    for (int p = 0; p < NST - 1; p++)
        if (p < nC) { ldStage(p, p); cp_commit(); } else { cp_commit(); }

    for (int c = 0; c < nC; c++) {
        const int rem = nC - 1 - c;
        int tgt = NST - 2; if (rem < tgt) tgt = rem;
        switch (tgt) {
            case 0: cp_wait<0>(); break;
            case 1: cp_wait<1>(); break;
            case 2: cp_wait<2>(); break;
            case 3: cp_wait<3>(); break;
            default: cp_wait<4>(); break;
        }
        __syncthreads();
        if (c + NST - 1 < nC) { ldStage(c + NST - 1, (c + NST - 1) % NST); cp_commit(); }

        const u32 tb = smb + (c % NST) * STRIDE;
        #pragma unroll
        for (int s16 = 0; s16 < 2; s16++) {
            u32 bh[8], bl[8];
            const u32 rb = (u32)((wn * 32 + rBl) * 64 +
                                 (((2 * s16 + csB) ^ xB) << 4));
            LDMX4(bh[0], bh[1], bh[2], bh[3], tb + OB + rb);
            LDMX4(bh[4], bh[5], bh[6], bh[7], tb + OB + rb + 1024);
            if constexpr (NPASS >= 3) {
                LDMX4(bl[0], bl[1], bl[2], bl[3], tb + 24576 + rb);
                LDMX4(bl[4], bl[5], bl[6], bl[7], tb + 24576 + rb + 1024);
            }
            #pragma unroll
            for (int mt = 0; mt < 4; mt++) {
                u32 ah[4], al[4];
                const u32 ra = (u32)((wm * 64 + mt * 16 + rAl) * 64 +
                                     (((2 * s16 + ksA) ^ xA) << 4));
                LDMX4(ah[0], ah[1], ah[2], ah[3], tb + ra);
                if constexpr (NPASS >= 2)
                    LDMX4(al[0], al[1], al[2], al[3], tb + 8192 + ra);
                #pragma unroll
                for (int nt = 0; nt < 4; nt++) {
                    MMA16816(acc[mt][nt], ah, bh[2*nt], bh[2*nt+1]);
                    if constexpr (NPASS >= 3)
                        MMA16816(acc[mt][nt], ah, bl[2*nt], bl[2*nt+1]);
                    if constexpr (NPASS >= 2)
                        MMA16816(acc[mt][nt], al, bh[2*nt], bh[2*nt+1]);
                }
            }
        }
    }

    // epilogue
    if (WHT) __syncthreads();
    __half* T = (__half*)sm;

    const float gm = RESID ? gamma[0] : 0.0f;
    #pragma unroll
    for (int mt = 0; mt < 4; mt++) {
        #pragma unroll
        for (int nt = 0; nt < 4; nt++) {
            const int nn = wn * 32 + nt * 8 + (lid & 3) * 2;
            #pragma unroll
            for (int h = 0; h < 2; h++) {
                const int ml = wm * 64 + mt * 16 + (lid >> 2) + h * 8;
                const int mm = m0 + ml;
                float v0 = acc[mt][nt][2 * h];
                float v1 = acc[mt][nt][2 * h + 1];
                if (RESID) {
                    const size_t off = (size_t)mm * ldC + n0 + nn;
                    const __half2 rh = *(const __half2*)(Rh + off);
                    const __half2 rl = *(const __half2*)(Rl + off);
                    v0 = gm * v0 + __low2float(rh)  + __low2float(rl);
                    v1 = gm * v1 + __high2float(rh) + __high2float(rl);
                }
                if (WN)
                    *(float2*)(Cb + (size_t)mm * ldC + n0 + nn) =
                        make_float2(v0, v1);
                if (WHT) {
                    T[(size_t)nn * 136 + ml]       = __float2half_rn(v0);
                    T[(size_t)(nn + 1) * 136 + ml] = __float2half_rn(v1);
                }
            }
        }
    }

    if (WHT) {
        __syncthreads();
        #pragma unroll
        for (int it = 0; it < 8; it++) {
            const int idx = it * 256 + tid;
            const int n  = idx >> 4;
            const int ck = idx & 15;
            const uint4 v = *(const uint4*)(T + (size_t)n * 136 + ck * 8);
            *(uint4*)(CThb + (size_t)(n0 + n) * ldT + m0 + ck * 8) = v;
        }
    }
}

// ===========================================================================
// Merged weight split: three fp32->fp16 hi/lo splits in one launch.
// ===========================================================================
static const int NW1 = 256 * 512;
static const int NW2 = 256 * 320;
static const int NW3 = 512 * 256;

__global__ __launch_bounds__(256)
void split_w3(const float* __restrict__ w1, const float* __restrict__ w2,
              const float* __restrict__ w3,
              __half* __restrict__ o1h, __half* __restrict__ o1l,
              __half* __restrict__ o2h, __half* __restrict__ o2l,
              __half* __restrict__ o3h, __half* __restrict__ o3l)
{
    int i = blockIdx.x * 256 + threadIdx.x;
    const float* in; __half *oh, *ol;
    if (i < NW1)                  { in = w1; oh = o1h; ol = o1l; }
    else if (i < NW1 + NW2)       { i -= NW1; in = w2; oh = o2h; ol = o2l; }
    else if (i < NW1 + NW2 + NW3) { i -= NW1 + NW2; in = w3; oh = o3h; ol = o3l; }
    else return;
    const float v = in[i];
    const __half hh = __float2half_rn(v);
    oh[i] = hh;
    ol[i] = __float2half_rn(v - __half2float(hh));
}

// ===========================================================================
// Softmax over rows of 256 (sums NSPLIT partials), warp-shuffle reductions.
// Emits fp16 hi only (stage 5 is 1-pass).
// ===========================================================================
__global__ __launch_bounds__(256)
void softmax_rows(const float* __restrict__ P, __half* __restrict__ Ah)
{
    const size_t RS = (size_t)BATCH * CCH * CCH;
    const int row = blockIdx.x;
    const int tid = threadIdx.x;
    const int lid = tid & 31;
    const int wrp = tid >> 5;
    const size_t base = (size_t)row * CCH + tid;
    float x = 0.0f;
    #pragma unroll
    for (int s = 0; s < NSPLIT; s++) x += P[s * RS + base];

    __shared__ float red[8];
    float m = x;
    #pragma unroll
    for (int o = 16; o > 0; o >>= 1)
        m = fmaxf(m, __shfl_xor_sync(0xFFFFFFFFu, m, o));
    if (lid == 0) red[wrp] = m;
    __syncthreads();
    float mx = red[0];
    #pragma unroll
    for (int w = 1; w < 8; w++) mx = fmaxf(mx, red[w]);

    const float e = expf(x - mx);
    float sum = e;
    #pragma unroll
    for (int o = 16; o > 0; o >>= 1)
        sum += __shfl_xor_sync(0xFFFFFFFFu, sum, o);
    __syncthreads();
    if (lid == 0) red[wrp] = sum;
    __syncthreads();
    float tot = 0.0f;
    #pragma unroll
    for (int w = 0; w < 8; w++) tot += red[w];

    Ah[base] = __float2half_rn(e / tot);
}

// ===========================================================================
// Launch
// ===========================================================================
extern "C" void kernel_launch(void* const* d_in, const int* in_sizes, int n_in,
                              void* d_out, int out_size)
{
    const float* x1    = (const float*)d_in[0];
    const float* x2    = (const float*)d_in[1];
    const float* w_img = (const float*)d_in[2];
    const float* w_txt = (const float*)d_in[3];
    const float* w_out = (const float*)d_in[4];
    const float* gamma = (const float*)d_in[5];
    float* out = (float*)d_out;

    __half *wih, *wil, *wth, *wtl, *woh, *wol;
    __half *imgh, *imgl, *kvh, *kvl, *kvTh, *tTh, *atth;
    float *part;
    cudaGetSymbolAddress((void**)&wih,  g_wih);
    cudaGetSymbolAddress((void**)&wil,  g_wil);
    cudaGetSymbolAddress((void**)&wth,  g_wth);
    cudaGetSymbolAddress((void**)&wtl,  g_wtl);
    cudaGetSymbolAddress((void**)&woh,  g_woh);
    cudaGetSymbolAddress((void**)&wol,  g_wol);
    cudaGetSymbolAddress((void**)&imgh, g_imgh);
    cudaGetSymbolAddress((void**)&imgl, g_imgl);
    cudaGetSymbolAddress((void**)&kvh,  g_kvh);
    cudaGetSymbolAddress((void**)&kvl,  g_kvl);
    cudaGetSymbolAddress((void**)&kvTh, g_kvTh);
    cudaGetSymbolAddress((void**)&tTh,  g_tTh);
    cudaGetSymbolAddress((void**)&part, g_part);
    cudaGetSymbolAddress((void**)&atth, g_atth);

    cudaFuncSetAttribute(gemm_fused,
                         cudaFuncAttributeMaxDynamicSharedMemorySize, SMEM_F);
    cudaFuncSetAttribute(gemm_mma<false, true,  false, 3>,
                         cudaFuncAttributeMaxDynamicSharedMemorySize, SMEM_TOT);
    cudaFuncSetAttribute(gemm_mma<true,  false, true,  1>,
                         cudaFuncAttributeMaxDynamicSharedMemorySize, SMEM_TOT);
    cudaFuncSetAttribute(gemm_mma<false, true,  false, 1>,
                         cudaFuncAttributeMaxDynamicSharedMemorySize, SMEM_TOT);

    // 0) all weight splits in one launch
    split_w3<<<(NW1 + NW2 + NW3 + 255) / 256, 256>>>(
        w_img, w_txt, w_out, wih, wil, wth, wtl, woh, wol);

    // 1+2) img & kv projections, fused transpose+split, one launch
    gemm_fused<<<dim3(32, 2, 32), 256, SMEM_F>>>(
        wih, wil, x1, imgh, imgl,
        wth, wtl, x2, kvh, kvl, kvTh);

    // 3) logits partials (3-pass, split-K=8)
    gemm_mma<false, true, false, 3><<<dim3(2, 2, 16 * NSPLIT), 256, SMEM_TOT>>>(
        imgh, imgl, kvh, kvl, part, nullptr, nullptr, nullptr, nullptr,
        NSP / NSPLIT, 4096, 4096, 256, 0,
        256L * 4096, 256L * 4096, 256L * 256, 0L, NSPLIT);

    // 4) softmax (hi only)
    softmax_rows<<<BATCH * CCH, 256>>>(part, atth);

    // 5) tT[n,c] = gamma*(attn @ kvT) + (imgh+imgl)  (1-pass, 6-stage)
    gemm_mma<true, false, true, 1><<<dim3(32, 2, 16), 256, SMEM_TOT>>>(
        atth, nullptr, kvTh, nullptr, nullptr, tTh, imgh, imgl, gamma,
        256, 256, 256, 4096, 256,
        256L * 256, 4096L * 256, 256L * 4096, 4096L * 256, 1);

    // 6) out = w_out @ tT  (1-pass, 6-stage)
    gemm_mma<false, true, false, 1><<<dim3(32, 4, 16), 256, SMEM_TOT>>>(
        woh, nullptr, tTh, nullptr, out, nullptr, nullptr, nullptr, nullptr,
        256, 256, 256, 4096, 0,
        0L, 4096L * 256, 512L * 4096, 0L, 1);
}